// round 11
// baseline (speedup 1.0000x reference)
#include <cuda_runtime.h>
#include <cuda_bf16.h>
#include <cstdint>
#include <cstddef>

#define VOCAB  32000
#define HIDDEN 1024
#define BATCH  8
#define SEQ    512
#define G4     (4*HIDDEN)       // 4096
#define MROWS  (BATCH*SEQ)      // 4096
#define LP_BLOCKS 128

// ---------------- static device scratch (no allocs allowed) ----------------
__device__ float g_emb[(size_t)MROWS * HIDDEN];          // [m][h], m = s*8+b
__device__ float g_xg [(size_t)MROWS * G4];              // [m][4H]
__device__ float g_hs [(size_t)MROWS * HIDDEN];          // [m][h]
__device__ float g_WhT[(size_t)G4 * HIDDEN];             // [col][k]
__device__ float g_h  [2 * BATCH * HIDDEN];              // double-buffered h
__device__ float g_c  [BATCH * HIDDEN];
__device__ int   g_ids[MROWS];
__device__ unsigned g_bar;                               // persistent-grid barrier
// bf16 split operands for tensor-core logits GEMM
__device__ __nv_bfloat16 g_hs_hi[(size_t)MROWS * HIDDEN];   // [m][k]
__device__ __nv_bfloat16 g_hs_lo[(size_t)MROWS * HIDDEN];
__device__ __nv_bfloat16 g_WT_hi[(size_t)VOCAB * HIDDEN];   // [v][k]
__device__ __nv_bfloat16 g_WT_lo[(size_t)VOCAB * HIDDEN];

// ================= base-target tensor-core helpers =================
#define CP_ASYNC16(dst, src) \
    asm volatile("cp.async.cg.shared.global [%0], [%1], 16;" :: "r"(dst), "l"(src))
#define CP_COMMIT() asm volatile("cp.async.commit_group;" ::: "memory")
#define CP_WAIT(n)  asm volatile("cp.async.wait_group %0;" :: "n"(n) : "memory")

__device__ __forceinline__ uint32_t smem_u32(const void* p) {
    uint32_t a;
    asm("{ .reg .u64 t; cvta.to.shared.u64 t, %1; cvt.u32.u64 %0, t; }" : "=r"(a) : "l"(p));
    return a;
}
__device__ __forceinline__ void ldmx4(uint32_t* r, uint32_t addr) {
    asm volatile("ldmatrix.sync.aligned.m8n8.x4.shared.b16 {%0,%1,%2,%3}, [%4];"
                 : "=r"(r[0]), "=r"(r[1]), "=r"(r[2]), "=r"(r[3]) : "r"(addr));
}
__device__ __forceinline__ void mma16816(float* c, const uint32_t* a, const uint32_t* b) {
    asm volatile("mma.sync.aligned.m16n8k16.row.col.f32.bf16.bf16.f32 "
                 "{%0,%1,%2,%3}, {%4,%5,%6,%7}, {%8,%9}, {%0,%1,%2,%3};"
                 : "+f"(c[0]), "+f"(c[1]), "+f"(c[2]), "+f"(c[3])
                 : "r"(a[0]), "r"(a[1]), "r"(a[2]), "r"(a[3]), "r"(b[0]), "r"(b[1]));
}
// release-scope arrive + acquire poll for the grid barrier
__device__ __forceinline__ void bar_arrive() {
    unsigned dummy;
    asm volatile("atom.add.release.gpu.u32 %0, [%1], 1;"
                 : "=r"(dummy) : "l"(&g_bar) : "memory");
}
__device__ __forceinline__ unsigned bar_peek() {
    unsigned v;
    asm volatile("ld.acquire.gpu.u32 %0, [%1];" : "=r"(v) : "l"(&g_bar) : "memory");
    return v;
}

// ---------------- init: zero h, c, barrier ----------------
__global__ void init_state_kernel() {
    int i = blockIdx.x * 256 + threadIdx.x;
    if (i < 2 * BATCH * HIDDEN) g_h[i] = 0.f;
    if (i < BATCH * HIDDEN)     g_c[i] = 0.f;
    if (i == 0)                 g_bar = 0u;
}

// ---------------- dtype-agnostic id decode ----------------
__global__ void decode_ids_kernel(const int* __restrict__ raw) {
    __shared__ int is64;
    if (threadIdx.x == 0) {
        int allzero = 1;
        for (int i = 0; i < 128; ++i)
            if (raw[2 * i + 1] != 0) { allzero = 0; break; }
        is64 = allzero;
    }
    __syncthreads();
    int i = blockIdx.x * 256 + threadIdx.x;
    if (i < MROWS) {
        int v = is64 ? raw[2 * i] : raw[i];
        if (v < 0) v = 0;
        if (v >= VOCAB) v = VOCAB - 1;
        g_ids[i] = v;
    }
}

// ---------------- embedding gather ----------------
__global__ void gather_kernel(const float* __restrict__ Wout) {
    int idx = blockIdx.x * 256 + threadIdx.x;
    int m = idx >> 10;
    int h = idx & 1023;
    int b = m & 7, s = m >> 3;
    int id = g_ids[b * SEQ + s];
    g_emb[idx] = Wout[(size_t)h * VOCAB + (size_t)id];
}

// ---------------- Wh transpose ----------------
__global__ void transpose_wh_kernel(const float* __restrict__ Wh) {
    __shared__ float t[32][33];
    int bx = blockIdx.x, by = blockIdx.y;
    int x = threadIdx.x, y = threadIdx.y;
#pragma unroll
    for (int i = 0; i < 4; ++i)
        t[y + i * 8][x] = Wh[(size_t)(bx * 32 + y + i * 8) * G4 + by * 32 + x];
    __syncthreads();
#pragma unroll
    for (int i = 0; i < 4; ++i)
        g_WhT[(size_t)(by * 32 + y + i * 8) * HIDDEN + bx * 32 + x] = t[x][y + i * 8];
}

// ---------------- split hs -> bf16 hi/lo ----------------
__global__ void split_hs_kernel() {
    int i = (blockIdx.x * 256 + threadIdx.x) * 4;
    float4 v = *(const float4*)&g_hs[i];
    float vv[4] = {v.x, v.y, v.z, v.w};
#pragma unroll
    for (int j = 0; j < 4; ++j) {
        __nv_bfloat16 hi = __float2bfloat16(vv[j]);
        g_hs_hi[i + j] = hi;
        g_hs_lo[i + j] = __float2bfloat16(vv[j] - __bfloat162float(hi));
    }
}

// ---------------- W_out transpose + split: WT[v][k] bf16 hi/lo ----------------
__global__ void split_wout_kernel(const float* __restrict__ W) {
    __shared__ float t[32][33];
    int v0 = blockIdx.x * 32, k0 = blockIdx.y * 32;
    int x = threadIdx.x, y = threadIdx.y;
#pragma unroll
    for (int i = 0; i < 4; ++i)
        t[y + i * 8][x] = W[(size_t)(k0 + y + i * 8) * VOCAB + v0 + x];   // t[k][v]
    __syncthreads();
#pragma unroll
    for (int i = 0; i < 4; ++i) {
        float val = t[x][y + i * 8];
        __nv_bfloat16 hi = __float2bfloat16(val);
        size_t o = (size_t)(v0 + y + i * 8) * HIDDEN + k0 + x;
        g_WT_hi[o] = hi;
        g_WT_lo[o] = __float2bfloat16(val - __bfloat162float(hi));
    }
}

// ---------------- 128x128x16 double-buffered fp32 SGEMM (x_gates) ----------------
template <int PERM>
__global__ __launch_bounds__(256, 2) void sgemm128(const float* __restrict__ A,
                                                   const float* __restrict__ B,
                                                   const float* __restrict__ bias,
                                                   float* __restrict__ C,
                                                   int M, int N, int K) {
    __shared__ float As[2][16][128];
    __shared__ float Bs[2][16][128];

    const int tid = threadIdx.x;
    const int bx = blockIdx.x, by = blockIdx.y;
    const int tx = tid & 15, ty = tid >> 4;
    const int arow = tid >> 1, acol = (tid & 1) * 8;
    const int brow = tid >> 5, bcol = (tid & 31) * 4;

    const float* Ab = A + (size_t)(by * 128 + arow) * K + acol;
    const float* Bb = B + (size_t)(bx * 128) + bcol;

    float4 a0r = *(const float4*)(Ab + 0);
    float4 a1r = *(const float4*)(Ab + 4);
    float4 b0r = *(const float4*)(Bb + (size_t)brow * N);
    float4 b1r = *(const float4*)(Bb + (size_t)(brow + 8) * N);

    As[0][acol + 0][arow] = a0r.x;  As[0][acol + 1][arow] = a0r.y;
    As[0][acol + 2][arow] = a0r.z;  As[0][acol + 3][arow] = a0r.w;
    As[0][acol + 4][arow] = a1r.x;  As[0][acol + 5][arow] = a1r.y;
    As[0][acol + 6][arow] = a1r.z;  As[0][acol + 7][arow] = a1r.w;
    *(float4*)&Bs[0][brow][bcol]     = b0r;
    *(float4*)&Bs[0][brow + 8][bcol] = b1r;
    __syncthreads();

    float acc[8][8];
#pragma unroll
    for (int i = 0; i < 8; ++i)
#pragma unroll
        for (int j = 0; j < 8; ++j) acc[i][j] = 0.f;

    int buf = 0;
    for (int k0 = 16; k0 < K; k0 += 16) {
        a0r = *(const float4*)(Ab + k0);
        a1r = *(const float4*)(Ab + k0 + 4);
        b0r = *(const float4*)(Bb + (size_t)(k0 + brow) * N);
        b1r = *(const float4*)(Bb + (size_t)(k0 + brow + 8) * N);

#pragma unroll
        for (int k = 0; k < 16; ++k) {
            float4 A0 = *(const float4*)&As[buf][k][ty * 8];
            float4 A1 = *(const float4*)&As[buf][k][ty * 8 + 4];
            float4 B0 = *(const float4*)&Bs[buf][k][tx * 8];
            float4 B1 = *(const float4*)&Bs[buf][k][tx * 8 + 4];
            float af[8] = {A0.x, A0.y, A0.z, A0.w, A1.x, A1.y, A1.z, A1.w};
            float bf[8] = {B0.x, B0.y, B0.z, B0.w, B1.x, B1.y, B1.z, B1.w};
#pragma unroll
            for (int i = 0; i < 8; ++i)
#pragma unroll
                for (int j = 0; j < 8; ++j)
                    acc[i][j] = fmaf(af[i], bf[j], acc[i][j]);
        }

        int nb = buf ^ 1;
        As[nb][acol + 0][arow] = a0r.x;  As[nb][acol + 1][arow] = a0r.y;
        As[nb][acol + 2][arow] = a0r.z;  As[nb][acol + 3][arow] = a0r.w;
        As[nb][acol + 4][arow] = a1r.x;  As[nb][acol + 5][arow] = a1r.y;
        As[nb][acol + 6][arow] = a1r.z;  As[nb][acol + 7][arow] = a1r.w;
        *(float4*)&Bs[nb][brow][bcol]     = b0r;
        *(float4*)&Bs[nb][brow + 8][bcol] = b1r;
        __syncthreads();
        buf = nb;
    }

#pragma unroll
    for (int k = 0; k < 16; ++k) {
        float4 A0 = *(const float4*)&As[buf][k][ty * 8];
        float4 A1 = *(const float4*)&As[buf][k][ty * 8 + 4];
        float4 B0 = *(const float4*)&Bs[buf][k][tx * 8];
        float4 B1 = *(const float4*)&Bs[buf][k][tx * 8 + 4];
        float af[8] = {A0.x, A0.y, A0.z, A0.w, A1.x, A1.y, A1.z, A1.w};
        float bf[8] = {B0.x, B0.y, B0.z, B0.w, B1.x, B1.y, B1.z, B1.w};
#pragma unroll
        for (int i = 0; i < 8; ++i)
#pragma unroll
            for (int j = 0; j < 8; ++j)
                acc[i][j] = fmaf(af[i], bf[j], acc[i][j]);
    }

    const int ncol0 = bx * 128 + tx * 8;
    float bv[8];
#pragma unroll
    for (int j = 0; j < 8; ++j) bv[j] = bias[ncol0 + j];

#pragma unroll
    for (int i = 0; i < 8; ++i) {
        int m = by * 128 + ty * 8 + i;
        size_t crow;
        if (PERM) crow = (size_t)((m & 7) * SEQ + (m >> 3));
        else      crow = (size_t)m;
        float* Cr = C + crow * (size_t)N + ncol0;
#pragma unroll
        for (int j = 0; j < 8; ++j) Cr[j] = acc[i][j] + bv[j];
    }
}

// ================= persistent LSTM recurrence =================
// 128 blocks x 256 threads, 1 block/SM (192KB dyn smem) -> all co-resident in
// wave 1 (128 <= 148 SMs), so the grid spin-barrier cannot deadlock.
// Block owns j in [bx*8, bx*8+8) across all 4 gates; Wh slice cached in smem
// for all 512 steps. Cross-block h exchange through L2 with acq/rel atomics.
__global__ __launch_bounds__(256, 1) void lstm_persistent_kernel() {
    extern __shared__ float sm[];
    float* wsm  = sm;                       // [k][jl][g] 1024*8*4 f (128KB)
    float* h_s  = sm + 32768;               // [k][b]     1024*8 f  (32KB)
    float* part = sm + 32768 + 8192;        // [ks][jl][g][b] 32*8*4*8 (32KB)

    const int tid = threadIdx.x;
    const int j0  = blockIdx.x * 8;

    // preload weights: wsm[(k*8 + jl)*4 + g] = WhT[g*1024 + j0 + jl][k]
    for (int i = tid; i < 8 * 1024; i += 256) {
        int jl = i & 7, k = i >> 3;
#pragma unroll
        for (int g = 0; g < 4; ++g)
            wsm[(k * 8 + jl) * 4 + g] =
                g_WhT[(size_t)(g * HIDDEN + j0 + jl) * HIDDEN + k];
    }

    const int jl = tid & 7;
    const int ks = tid >> 3;                // 0..31
    const int kbase = ks * 32;

    // finalize-thread state (tid < 64): c kept in a register for all steps
    float c_reg = 0.f;
    const int fjl = tid & 7, fb = tid >> 3;
    const int fj = j0 + fjl;

    __syncthreads();

    for (int t = 0; t < SEQ; ++t) {
        const float* hin = g_h + (t & 1) * (BATCH * HIDDEN);
        // load h transposed into h_s[k*8+b]; __ldcg bypasses (possibly stale) L1
        for (int i = tid * 4; i < BATCH * HIDDEN; i += 1024) {
            float4 v = __ldcg((const float4*)(hin + i));
            int b = i >> 10, k = i & 1023;
            h_s[(k + 0) * 8 + b] = v.x;
            h_s[(k + 1) * 8 + b] = v.y;
            h_s[(k + 2) * 8 + b] = v.z;
            h_s[(k + 3) * 8 + b] = v.w;
        }
        __syncthreads();

        float acc[4][8];
#pragma unroll
        for (int g = 0; g < 4; ++g)
#pragma unroll
            for (int b = 0; b < 8; ++b) acc[g][b] = 0.f;

#pragma unroll 4
        for (int c = 0; c < 32; ++c) {
            int k = kbase + c;
            float4 w  = *(const float4*)&wsm[(k * 8 + jl) * 4];
            float4 h0 = *(const float4*)&h_s[k * 8];
            float4 h1 = *(const float4*)&h_s[k * 8 + 4];
            float hb[8] = {h0.x, h0.y, h0.z, h0.w, h1.x, h1.y, h1.z, h1.w};
            float wg[4] = {w.x, w.y, w.z, w.w};
#pragma unroll
            for (int g = 0; g < 4; ++g)
#pragma unroll
                for (int b = 0; b < 8; ++b)
                    acc[g][b] = fmaf(wg[g], hb[b], acc[g][b]);
        }
        float* pp = &part[((ks * 8 + jl) * 4) * 8];
#pragma unroll
        for (int g = 0; g < 4; ++g)
#pragma unroll
            for (int b = 0; b < 8; ++b) pp[g * 8 + b] = acc[g][b];
        __syncthreads();

        if (tid < 64) {
            float gs[4] = {0.f, 0.f, 0.f, 0.f};
#pragma unroll 8
            for (int s = 0; s < 32; ++s) {
                const float* q = &part[((s * 8 + fjl) * 4) * 8 + fb];
#pragma unroll
                for (int g = 0; g < 4; ++g) gs[g] += q[g * 8];
            }
            const float* xg = &g_xg[((size_t)t * 8 + fb) * G4];
            float i_ = 1.f / (1.f + expf(-(gs[0] + xg[fj])));
            float f_ = 1.f / (1.f + expf(-(gs[1] + xg[HIDDEN + fj])));
            float g_ = tanhf(gs[2] + xg[2 * HIDDEN + fj]);
            float o_ = 1.f / (1.f + expf(-(gs[3] + xg[3 * HIDDEN + fj])));
            c_reg = f_ * c_reg + i_ * g_;
            float hn = o_ * tanhf(c_reg);
            g_h[((t + 1) & 1) * (BATCH * HIDDEN) + fb * HIDDEN + fj] = hn;
            g_hs[((size_t)t * 8 + fb) * HIDDEN + fj] = hn;
        }
        __syncthreads();
        // grid barrier: release-arrive, acquire-poll with nanosleep backoff
        if (tid == 0) {
            bar_arrive();
            const unsigned target = (unsigned)LP_BLOCKS * (unsigned)(t + 1);
            while (bar_peek() < target) __nanosleep(64);
        }
        __syncthreads();
    }
}

// ================= mma.sync bf16-split logits GEMM (3-stage) =================
// CTA tile 128x128, 8 warps (2 M x 4 N), warp tile 64x32, m16n8k16 HMMA.
// 3 products: Ahi*Bhi + Ahi*Blo + Alo*Bhi over K=1024, BK=32, cp.async 3-stage.
#define L_STRIDE  80                       // bytes per smem row (32 bf16 + 16B pad)
#define L_AB      (128 * L_STRIDE)         // 10240 bytes per tile
#define L_STAGE   (2 * L_AB)               // A + B per stage
#define L_NIT     96                       // 3 products x 32 k-chunks
#define L_SMEM    (3 * L_STAGE)            // 61440 bytes

__global__ __launch_bounds__(256) void logits_mma_kernel(float* __restrict__ out,
                                                         const float* __restrict__ bias) {
    extern __shared__ char lsm[];
    const uint32_t sbase = smem_u32(lsm);

    const int tid  = threadIdx.x;
    const int lane = tid & 31;
    const int wid  = tid >> 5;
    const int wm   = wid >> 2;             // 0..1
    const int wn   = wid & 3;              // 0..3
    const int m0   = blockIdx.x * 128;
    const int n0   = blockIdx.y * 128;

    const int lrow = tid >> 2;             // 0..63
    const int lch  = tid & 3;              // 16B chunk

    float acc[4][4][4];
#pragma unroll
    for (int i = 0; i < 4; ++i)
#pragma unroll
        for (int j = 0; j < 4; ++j)
#pragma unroll
            for (int k = 0; k < 4; ++k) acc[i][j][k] = 0.f;

    auto load_stage = [&](int it, int s) {
        const int p  = it >> 5;
        const int k0 = (it & 31) * 32;
        const __nv_bfloat16* Asrc = (p < 2) ? g_hs_hi : g_hs_lo;
        const __nv_bfloat16* Bsrc = (p == 1) ? g_WT_lo : g_WT_hi;
        uint32_t sa = sbase + s * L_STAGE;
        uint32_t sb = sa + L_AB;
#pragma unroll
        for (int rr = 0; rr < 128; rr += 64) {
            const __nv_bfloat16* srcA = Asrc + (size_t)(m0 + lrow + rr) * HIDDEN + k0 + lch * 8;
            CP_ASYNC16(sa + (lrow + rr) * L_STRIDE + lch * 16, srcA);
            const __nv_bfloat16* srcB = Bsrc + (size_t)(n0 + lrow + rr) * HIDDEN + k0 + lch * 8;
            CP_ASYNC16(sb + (lrow + rr) * L_STRIDE + lch * 16, srcB);
        }
        CP_COMMIT();
    };

    load_stage(0, 0);
    load_stage(1, 1);

    for (int it = 0; it < L_NIT; ++it) {
        if (it + 2 < L_NIT) {
            load_stage(it + 2, (it + 2) % 3);
            CP_WAIT(2);
        } else {
            CP_WAIT(0);
        }
        __syncthreads();

        uint32_t sa = sbase + (it % 3) * L_STAGE;
        uint32_t sb = sa + L_AB;
#pragma unroll
        for (int k16 = 0; k16 < 2; ++k16) {
            const uint32_t koff = k16 * 32 + (lane >> 4) * 16;
            uint32_t a[4][4];
#pragma unroll
            for (int mf = 0; mf < 4; ++mf)
                ldmx4(a[mf], sa + (wm * 64 + mf * 16 + (lane & 15)) * L_STRIDE + koff);
            uint32_t bfr[4][2];
#pragma unroll
            for (int nh = 0; nh < 2; ++nh) {
                uint32_t t4[4];
                ldmx4(t4, sb + (wn * 32 + nh * 16 + (lane & 15)) * L_STRIDE + koff);
                bfr[nh * 2 + 0][0] = t4[0]; bfr[nh * 2 + 0][1] = t4[2];
                bfr[nh * 2 + 1][0] = t4[1]; bfr[nh * 2 + 1][1] = t4[3];
            }
#pragma unroll
            for (int mf = 0; mf < 4; ++mf)
#pragma unroll
                for (int nf = 0; nf < 4; ++nf)
                    mma16816(acc[mf][nf], a[mf], bfr[nf]);
        }
        __syncthreads();
    }

    // epilogue: bias + (b,s) permute
#pragma unroll
    for (int mf = 0; mf < 4; ++mf) {
        const int mbase = m0 + wm * 64 + mf * 16;
        const int m1 = mbase + (lane >> 2);
        const int m2 = m1 + 8;
        const size_t r1 = (size_t)((m1 & 7) * SEQ + (m1 >> 3)) * VOCAB;
        const size_t r2 = (size_t)((m2 & 7) * SEQ + (m2 >> 3)) * VOCAB;
#pragma unroll
        for (int nf = 0; nf < 4; ++nf) {
            const int n = n0 + wn * 32 + nf * 8 + (lane & 3) * 2;
            const float b0 = bias[n], b1 = bias[n + 1];
            float2 o1 = {acc[mf][nf][0] + b0, acc[mf][nf][1] + b1};
            float2 o2 = {acc[mf][nf][2] + b0, acc[mf][nf][3] + b1};
            *(float2*)(out + r1 + n) = o1;
            *(float2*)(out + r2 + n) = o2;
        }
    }
}

// ---------------- launch ----------------
extern "C" void kernel_launch(void* const* d_in, const int* in_sizes, int n_in,
                              void* d_out, int out_size) {
    const int*   ids_raw  = (const int*)d_in[0];
    const float* W_out    = (const float*)d_in[1];       // [H][V]
    const float* b_out    = (const float*)d_in[2];       // [V]
    const float* Wx       = (const float*)d_in[3];       // [H][4H]
    const float* Wh       = (const float*)d_in[4];       // [H][4H]
    const float* b_lstm   = (const float*)d_in[5];       // [4H]
    float* out            = (float*)d_out;               // [B][S][V]

    void *p_emb, *p_xg;
    cudaGetSymbolAddress(&p_emb, g_emb);
    cudaGetSymbolAddress(&p_xg,  g_xg);

    cudaFuncSetAttribute(lstm_persistent_kernel,
                         cudaFuncAttributeMaxDynamicSharedMemorySize, 192 * 1024);
    cudaFuncSetAttribute(logits_mma_kernel,
                         cudaFuncAttributeMaxDynamicSharedMemorySize, L_SMEM);

    // 0) zero h, c, barrier; decode ids; transpose Wh; split W_out
    init_state_kernel<<<(2 * BATCH * HIDDEN + 255) / 256, 256>>>();
    decode_ids_kernel<<<(MROWS + 255) / 256, 256>>>(ids_raw);
    {
        dim3 tg(HIDDEN / 32, G4 / 32);
        transpose_wh_kernel<<<tg, dim3(32, 8)>>>(Wh);
    }
    {
        dim3 wg(VOCAB / 32, HIDDEN / 32);
        split_wout_kernel<<<wg, dim3(32, 8)>>>(W_out);
    }

    // 1) embedding gather
    gather_kernel<<<(MROWS * HIDDEN) / 256, 256>>>(W_out);

    // 2) x_gates = emb @ Wx + b_lstm
    {
        dim3 grid(G4 / 128, MROWS / 128);
        sgemm128<0><<<grid, 256>>>((const float*)p_emb, Wx, b_lstm, (float*)p_xg,
                                   MROWS, G4, HIDDEN);
    }

    // 3) recurrence: single persistent kernel, 512 steps, global barrier per step
    lstm_persistent_kernel<<<LP_BLOCKS, 256, 192 * 1024>>>();

    // 4) split hs to bf16 hi/lo
    split_hs_kernel<<<(MROWS * HIDDEN / 4) / 256, 256>>>();

    // 5) logits = hs @ W_out + b_out via mma.sync bf16 3-product split
    {
        dim3 grid(MROWS / 128, VOCAB / 128);
        logits_mma_kernel<<<grid, 256, L_SMEM>>>(out, b_out);
    }
}

// round 12
// speedup vs baseline: 1.7102x; 1.7102x over previous
#include <cuda_runtime.h>
#include <cuda_bf16.h>
#include <cstdint>
#include <cstddef>

#define VOCAB  32000
#define HIDDEN 1024
#define BATCH  8
#define SEQ    512
#define G4     (4*HIDDEN)       // 4096
#define MROWS  (BATCH*SEQ)      // 4096
#define LP_BLOCKS 128

// ---------------- static device scratch (no allocs allowed) ----------------
__device__ float g_emb[(size_t)MROWS * HIDDEN];          // [m][h], m = s*8+b
__device__ float g_xg [(size_t)MROWS * G4];              // [m][4H]
__device__ float g_hs [(size_t)MROWS * HIDDEN];          // [m][h]
__device__ float g_WhT[(size_t)G4 * HIDDEN];             // [col][k]
__device__ float g_h  [2 * BATCH * HIDDEN];              // double-buffered h
__device__ int   g_ids[MROWS];
__device__ unsigned g_bar;                               // persistent-grid barrier
// bf16 split operands for tensor-core logits GEMM
__device__ __nv_bfloat16 g_hs_hi[(size_t)MROWS * HIDDEN];   // [m][k]
__device__ __nv_bfloat16 g_hs_lo[(size_t)MROWS * HIDDEN];
__device__ __nv_bfloat16 g_WT_hi[(size_t)VOCAB * HIDDEN];   // [v][k]
__device__ __nv_bfloat16 g_WT_lo[(size_t)VOCAB * HIDDEN];

// ================= helpers =================
#define CP_ASYNC16(dst, src) \
    asm volatile("cp.async.cg.shared.global [%0], [%1], 16;" :: "r"(dst), "l"(src))
#define CP_COMMIT() asm volatile("cp.async.commit_group;" ::: "memory")
#define CP_WAIT(n)  asm volatile("cp.async.wait_group %0;" :: "n"(n) : "memory")

__device__ __forceinline__ uint32_t smem_u32(const void* p) {
    uint32_t a;
    asm("{ .reg .u64 t; cvta.to.shared.u64 t, %1; cvt.u32.u64 %0, t; }" : "=r"(a) : "l"(p));
    return a;
}
__device__ __forceinline__ void ldmx4(uint32_t* r, uint32_t addr) {
    asm volatile("ldmatrix.sync.aligned.m8n8.x4.shared.b16 {%0,%1,%2,%3}, [%4];"
                 : "=r"(r[0]), "=r"(r[1]), "=r"(r[2]), "=r"(r[3]) : "r"(addr));
}
__device__ __forceinline__ void mma16816(float* c, const uint32_t* a, const uint32_t* b) {
    asm volatile("mma.sync.aligned.m16n8k16.row.col.f32.bf16.bf16.f32 "
                 "{%0,%1,%2,%3}, {%4,%5,%6,%7}, {%8,%9}, {%0,%1,%2,%3};"
                 : "+f"(c[0]), "+f"(c[1]), "+f"(c[2]), "+f"(c[3])
                 : "r"(a[0]), "r"(a[1]), "r"(a[2]), "r"(a[3]), "r"(b[0]), "r"(b[1]));
}
__device__ __forceinline__ void bar_arrive() {
    unsigned dummy;
    asm volatile("atom.add.release.gpu.u32 %0, [%1], 1;"
                 : "=r"(dummy) : "l"(&g_bar) : "memory");
}
__device__ __forceinline__ unsigned bar_peek() {
    unsigned v;
    asm volatile("ld.acquire.gpu.u32 %0, [%1];" : "=r"(v) : "l"(&g_bar) : "memory");
    return v;
}

// ---------------- init: zero h, barrier ----------------
__global__ void init_state_kernel() {
    int i = blockIdx.x * 256 + threadIdx.x;
    if (i < 2 * BATCH * HIDDEN) g_h[i] = 0.f;
    if (i == 0)                 g_bar = 0u;
}

// ---------------- dtype-agnostic id decode ----------------
__global__ void decode_ids_kernel(const int* __restrict__ raw) {
    __shared__ int is64;
    if (threadIdx.x == 0) {
        int allzero = 1;
        for (int i = 0; i < 128; ++i)
            if (raw[2 * i + 1] != 0) { allzero = 0; break; }
        is64 = allzero;
    }
    __syncthreads();
    int i = blockIdx.x * 256 + threadIdx.x;
    if (i < MROWS) {
        int v = is64 ? raw[2 * i] : raw[i];
        if (v < 0) v = 0;
        if (v >= VOCAB) v = VOCAB - 1;
        g_ids[i] = v;
    }
}

// ---------------- embedding gather ----------------
__global__ void gather_kernel(const float* __restrict__ Wout) {
    int idx = blockIdx.x * 256 + threadIdx.x;
    int m = idx >> 10;
    int h = idx & 1023;
    int b = m & 7, s = m >> 3;
    int id = g_ids[b * SEQ + s];
    g_emb[idx] = Wout[(size_t)h * VOCAB + (size_t)id];
}

// ---------------- Wh transpose ----------------
__global__ void transpose_wh_kernel(const float* __restrict__ Wh) {
    __shared__ float t[32][33];
    int bx = blockIdx.x, by = blockIdx.y;
    int x = threadIdx.x, y = threadIdx.y;
#pragma unroll
    for (int i = 0; i < 4; ++i)
        t[y + i * 8][x] = Wh[(size_t)(bx * 32 + y + i * 8) * G4 + by * 32 + x];
    __syncthreads();
#pragma unroll
    for (int i = 0; i < 4; ++i)
        g_WhT[(size_t)(by * 32 + y + i * 8) * HIDDEN + bx * 32 + x] = t[x][y + i * 8];
}

// ---------------- split hs -> bf16 hi/lo ----------------
__global__ void split_hs_kernel() {
    int i = (blockIdx.x * 256 + threadIdx.x) * 4;
    float4 v = *(const float4*)&g_hs[i];
    float vv[4] = {v.x, v.y, v.z, v.w};
#pragma unroll
    for (int j = 0; j < 4; ++j) {
        __nv_bfloat16 hi = __float2bfloat16(vv[j]);
        g_hs_hi[i + j] = hi;
        g_hs_lo[i + j] = __float2bfloat16(vv[j] - __bfloat162float(hi));
    }
}

// ---------------- W_out transpose + split: WT[v][k] bf16 hi/lo ----------------
__global__ void split_wout_kernel(const float* __restrict__ W) {
    __shared__ float t[32][33];
    int v0 = blockIdx.x * 32, k0 = blockIdx.y * 32;
    int x = threadIdx.x, y = threadIdx.y;
#pragma unroll
    for (int i = 0; i < 4; ++i)
        t[y + i * 8][x] = W[(size_t)(k0 + y + i * 8) * VOCAB + v0 + x];   // t[k][v]
    __syncthreads();
#pragma unroll
    for (int i = 0; i < 4; ++i) {
        float val = t[x][y + i * 8];
        __nv_bfloat16 hi = __float2bfloat16(val);
        size_t o = (size_t)(v0 + y + i * 8) * HIDDEN + k0 + x;
        g_WT_hi[o] = hi;
        g_WT_lo[o] = __float2bfloat16(val - __bfloat162float(hi));
    }
}

// ---------------- 128x128x16 double-buffered fp32 SGEMM (x_gates) ----------------
template <int PERM>
__global__ __launch_bounds__(256, 2) void sgemm128(const float* __restrict__ A,
                                                   const float* __restrict__ B,
                                                   const float* __restrict__ bias,
                                                   float* __restrict__ C,
                                                   int M, int N, int K) {
    __shared__ float As[2][16][128];
    __shared__ float Bs[2][16][128];

    const int tid = threadIdx.x;
    const int bx = blockIdx.x, by = blockIdx.y;
    const int tx = tid & 15, ty = tid >> 4;
    const int arow = tid >> 1, acol = (tid & 1) * 8;
    const int brow = tid >> 5, bcol = (tid & 31) * 4;

    const float* Ab = A + (size_t)(by * 128 + arow) * K + acol;
    const float* Bb = B + (size_t)(bx * 128) + bcol;

    float4 a0r = *(const float4*)(Ab + 0);
    float4 a1r = *(const float4*)(Ab + 4);
    float4 b0r = *(const float4*)(Bb + (size_t)brow * N);
    float4 b1r = *(const float4*)(Bb + (size_t)(brow + 8) * N);

    As[0][acol + 0][arow] = a0r.x;  As[0][acol + 1][arow] = a0r.y;
    As[0][acol + 2][arow] = a0r.z;  As[0][acol + 3][arow] = a0r.w;
    As[0][acol + 4][arow] = a1r.x;  As[0][acol + 5][arow] = a1r.y;
    As[0][acol + 6][arow] = a1r.z;  As[0][acol + 7][arow] = a1r.w;
    *(float4*)&Bs[0][brow][bcol]     = b0r;
    *(float4*)&Bs[0][brow + 8][bcol] = b1r;
    __syncthreads();

    float acc[8][8];
#pragma unroll
    for (int i = 0; i < 8; ++i)
#pragma unroll
        for (int j = 0; j < 8; ++j) acc[i][j] = 0.f;

    int buf = 0;
    for (int k0 = 16; k0 < K; k0 += 16) {
        a0r = *(const float4*)(Ab + k0);
        a1r = *(const float4*)(Ab + k0 + 4);
        b0r = *(const float4*)(Bb + (size_t)(k0 + brow) * N);
        b1r = *(const float4*)(Bb + (size_t)(k0 + brow + 8) * N);

#pragma unroll
        for (int k = 0; k < 16; ++k) {
            float4 A0 = *(const float4*)&As[buf][k][ty * 8];
            float4 A1 = *(const float4*)&As[buf][k][ty * 8 + 4];
            float4 B0 = *(const float4*)&Bs[buf][k][tx * 8];
            float4 B1 = *(const float4*)&Bs[buf][k][tx * 8 + 4];
            float af[8] = {A0.x, A0.y, A0.z, A0.w, A1.x, A1.y, A1.z, A1.w};
            float bf[8] = {B0.x, B0.y, B0.z, B0.w, B1.x, B1.y, B1.z, B1.w};
#pragma unroll
            for (int i = 0; i < 8; ++i)
#pragma unroll
                for (int j = 0; j < 8; ++j)
                    acc[i][j] = fmaf(af[i], bf[j], acc[i][j]);
        }

        int nb = buf ^ 1;
        As[nb][acol + 0][arow] = a0r.x;  As[nb][acol + 1][arow] = a0r.y;
        As[nb][acol + 2][arow] = a0r.z;  As[nb][acol + 3][arow] = a0r.w;
        As[nb][acol + 4][arow] = a1r.x;  As[nb][acol + 5][arow] = a1r.y;
        As[nb][acol + 6][arow] = a1r.z;  As[nb][acol + 7][arow] = a1r.w;
        *(float4*)&Bs[nb][brow][bcol]     = b0r;
        *(float4*)&Bs[nb][brow + 8][bcol] = b1r;
        __syncthreads();
        buf = nb;
    }

#pragma unroll
    for (int k = 0; k < 16; ++k) {
        float4 A0 = *(const float4*)&As[buf][k][ty * 8];
        float4 A1 = *(const float4*)&As[buf][k][ty * 8 + 4];
        float4 B0 = *(const float4*)&Bs[buf][k][tx * 8];
        float4 B1 = *(const float4*)&Bs[buf][k][tx * 8 + 4];
        float af[8] = {A0.x, A0.y, A0.z, A0.w, A1.x, A1.y, A1.z, A1.w};
        float bf[8] = {B0.x, B0.y, B0.z, B0.w, B1.x, B1.y, B1.z, B1.w};
#pragma unroll
        for (int i = 0; i < 8; ++i)
#pragma unroll
            for (int j = 0; j < 8; ++j)
                acc[i][j] = fmaf(af[i], bf[j], acc[i][j]);
    }

    const int ncol0 = bx * 128 + tx * 8;
    float bv[8];
#pragma unroll
    for (int j = 0; j < 8; ++j) bv[j] = bias[ncol0 + j];

#pragma unroll
    for (int i = 0; i < 8; ++i) {
        int m = by * 128 + ty * 8 + i;
        size_t crow;
        if (PERM) crow = (size_t)((m & 7) * SEQ + (m >> 3));
        else      crow = (size_t)m;
        float* Cr = C + crow * (size_t)N + ncol0;
#pragma unroll
        for (int j = 0; j < 8; ++j) Cr[j] = acc[i][j] + bv[j];
    }
}

// ================= persistent LSTM recurrence (conflict-free smem) =================
// 128 blocks x 256 threads, 1 block/SM. Warp w = jl (8 j-cols/block), lanes =
// 32 contiguous float4 k-chunks -> every LDS in the inner loop is lane-sequential
// 16B (conflict-free). h kept in natural [b][k] layout (no transpose). Partials
// reduced via pad-33 smem rows (conflict-free scalar reads by all 256 threads).
// smem floats: wsm 32768 | h_s 8192 | part 8448 | gsum 256  = 49664 (194 KB)
#define LP_SMEM_BYTES (49664 * 4)
__global__ __launch_bounds__(256, 1) void lstm_persistent_kernel() {
    extern __shared__ float sm[];
    float* wsm  = sm;              // [jl*4+g][k]  32 x 1024
    float* h_s  = sm + 32768;      // [b][k]       8 x 1024
    float* part = sm + 40960;      // [combo][33]  256 x 33
    float* gsum = sm + 49408;      // [256]

    const int tid = threadIdx.x;
    const int j0  = blockIdx.x * 8;
    const int wjl = tid >> 5;       // warp index = jl
    const int ln  = tid & 31;

    // preload weights: wsm[(jl*4+g)*1024 + k] = WhT[g*1024 + j0+jl][k]
    for (int f = tid; f < 8192; f += 256) {
        int jg = f >> 8;            // jl*4+g
        int jl = jg >> 2, g = jg & 3;
        int kq = (f & 255) * 4;
        float4 v = *(const float4*)&g_WhT[(size_t)(g * HIDDEN + j0 + jl) * HIDDEN + kq];
        *(float4*)&wsm[jg * 1024 + kq] = v;
    }

    // reduce mapping: combo = tid -> (rjl, rg, rb)
    const int rjl = tid >> 5, rg = (tid >> 3) & 3, rb = tid & 7;
    const int xg_col = rg * HIDDEN + j0 + rjl;
    // finalize mapping (tid < 64): (jl3, b3); c state lives here across steps
    float c_reg = 0.f;
    const int jl3 = tid >> 3, b3 = tid & 7;

    __syncthreads();

    for (int t = 0; t < SEQ; ++t) {
        // prefetch this thread's xg value (independent of h -> latency hidden)
        float xg_val = __ldg(&g_xg[((size_t)t * 8 + rb) * G4 + xg_col]);

        const float* hin = g_h + (t & 1) * (BATCH * HIDDEN);
        for (int i = tid * 4; i < BATCH * HIDDEN; i += 1024)
            *(float4*)&h_s[i] = __ldcg((const float4*)(hin + i));
        __syncthreads();

        float acc[4][8];
#pragma unroll
        for (int g = 0; g < 4; ++g)
#pragma unroll
            for (int b = 0; b < 8; ++b) acc[g][b] = 0.f;

        const float* wb = wsm + wjl * 4096;
#pragma unroll
        for (int c = 0; c < 8; ++c) {
            const int k = c * 128 + ln * 4;
            float4 w0 = *(const float4*)&wb[k];
            float4 w1 = *(const float4*)&wb[1024 + k];
            float4 w2 = *(const float4*)&wb[2048 + k];
            float4 w3 = *(const float4*)&wb[3072 + k];
#pragma unroll
            for (int b = 0; b < 8; ++b) {
                float4 hv = *(const float4*)&h_s[b * 1024 + k];
                acc[0][b] = fmaf(w0.x, hv.x, acc[0][b]);
                acc[0][b] = fmaf(w0.y, hv.y, acc[0][b]);
                acc[0][b] = fmaf(w0.z, hv.z, acc[0][b]);
                acc[0][b] = fmaf(w0.w, hv.w, acc[0][b]);
                acc[1][b] = fmaf(w1.x, hv.x, acc[1][b]);
                acc[1][b] = fmaf(w1.y, hv.y, acc[1][b]);
                acc[1][b] = fmaf(w1.z, hv.z, acc[1][b]);
                acc[1][b] = fmaf(w1.w, hv.w, acc[1][b]);
                acc[2][b] = fmaf(w2.x, hv.x, acc[2][b]);
                acc[2][b] = fmaf(w2.y, hv.y, acc[2][b]);
                acc[2][b] = fmaf(w2.z, hv.z, acc[2][b]);
                acc[2][b] = fmaf(w2.w, hv.w, acc[2][b]);
                acc[3][b] = fmaf(w3.x, hv.x, acc[3][b]);
                acc[3][b] = fmaf(w3.y, hv.y, acc[3][b]);
                acc[3][b] = fmaf(w3.z, hv.z, acc[3][b]);
                acc[3][b] = fmaf(w3.w, hv.w, acc[3][b]);
            }
        }
        // partials: lanes write consecutive floats -> conflict-free
#pragma unroll
        for (int g = 0; g < 4; ++g)
#pragma unroll
            for (int b = 0; b < 8; ++b)
                part[((wjl * 4 + g) * 8 + b) * 33 + ln] = acc[g][b];
        __syncthreads();

        // cross-lane reduce: thread tid sums its combo row (pad-33 -> conflict-free)
        {
            float s = 0.f;
            const float* pr = part + tid * 33;
#pragma unroll
            for (int i = 0; i < 32; ++i) s += pr[i];
            gsum[tid] = s + xg_val;
        }
        __syncthreads();

        if (tid < 64) {
            float gv0 = gsum[jl3 * 32 + 0 + b3];
            float gv1 = gsum[jl3 * 32 + 8 + b3];
            float gv2 = gsum[jl3 * 32 + 16 + b3];
            float gv3 = gsum[jl3 * 32 + 24 + b3];
            float i_ = 1.f / (1.f + expf(-gv0));
            float f_ = 1.f / (1.f + expf(-gv1));
            float gg = tanhf(gv2);
            float o_ = 1.f / (1.f + expf(-gv3));
            c_reg = f_ * c_reg + i_ * gg;
            float hn = o_ * tanhf(c_reg);
            int j = j0 + jl3;
            g_h[((t + 1) & 1) * (BATCH * HIDDEN) + b3 * HIDDEN + j] = hn;
            g_hs[((size_t)t * 8 + b3) * HIDDEN + j] = hn;
        }
        __syncthreads();
        if (tid == 0) {
            bar_arrive();                               // release: publishes h writes
            const unsigned target = (unsigned)LP_BLOCKS * (unsigned)(t + 1);
            while (bar_peek() < target) __nanosleep(32);
        }
        __syncthreads();
    }
}

// ================= mma.sync bf16-split logits GEMM (4-stage, 1 sync/iter) ========
// CTA tile 128x128, 8 warps (2 M x 4 N), warp tile 64x32, m16n8k16 HMMA.
// 3 products: Ahi*Bhi + Ahi*Blo + Alo*Bhi over K=1024, BK=32, cp.async 4-stage.
#define L_STRIDE  80                       // bytes per smem row (32 bf16 + 16B pad)
#define L_AB      (128 * L_STRIDE)         // 10240 bytes per tile
#define L_STAGE   (2 * L_AB)               // A + B per stage
#define L_NIT     96                       // 3 products x 32 k-chunks
#define L_SMEM    (4 * L_STAGE)            // 81920 bytes

__global__ __launch_bounds__(256, 2) void logits_mma_kernel(float* __restrict__ out,
                                                            const float* __restrict__ bias) {
    extern __shared__ char lsm[];
    const uint32_t sbase = smem_u32(lsm);

    const int tid  = threadIdx.x;
    const int lane = tid & 31;
    const int wid  = tid >> 5;
    const int wm   = wid >> 2;             // 0..1
    const int wn   = wid & 3;              // 0..3
    const int m0   = blockIdx.x * 128;
    const int n0   = blockIdx.y * 128;

    const int lrow = tid >> 2;             // 0..63
    const int lch  = tid & 3;              // 16B chunk

    float acc[4][4][4];
#pragma unroll
    for (int i = 0; i < 4; ++i)
#pragma unroll
        for (int j = 0; j < 4; ++j)
#pragma unroll
            for (int k = 0; k < 4; ++k) acc[i][j][k] = 0.f;

    auto load_stage = [&](int it, int s) {
        const int p  = it >> 5;
        const int k0 = (it & 31) * 32;
        const __nv_bfloat16* Asrc = (p < 2) ? g_hs_hi : g_hs_lo;
        const __nv_bfloat16* Bsrc = (p == 1) ? g_WT_lo : g_WT_hi;
        uint32_t sa = sbase + s * L_STAGE;
        uint32_t sb = sa + L_AB;
#pragma unroll
        for (int rr = 0; rr < 128; rr += 64) {
            const __nv_bfloat16* srcA = Asrc + (size_t)(m0 + lrow + rr) * HIDDEN + k0 + lch * 8;
            CP_ASYNC16(sa + (lrow + rr) * L_STRIDE + lch * 16, srcA);
            const __nv_bfloat16* srcB = Bsrc + (size_t)(n0 + lrow + rr) * HIDDEN + k0 + lch * 8;
            CP_ASYNC16(sb + (lrow + rr) * L_STRIDE + lch * 16, srcB);
        }
        CP_COMMIT();
    };

    load_stage(0, 0);
    load_stage(1, 1);

    for (int it = 0; it < L_NIT; ++it) {
        if (it + 2 < L_NIT) {
            load_stage(it + 2, (it + 2) & 3);
            CP_WAIT(2);
        } else {
            CP_WAIT(0);
        }
        __syncthreads();        // single sync: stage distance 3 keeps loads/readers apart

        uint32_t sa = sbase + (it & 3) * L_STAGE;
        uint32_t sb = sa + L_AB;
#pragma unroll
        for (int k16 = 0; k16 < 2; ++k16) {
            const uint32_t koff = k16 * 32 + (lane >> 4) * 16;
            uint32_t a[4][4];
#pragma unroll
            for (int mf = 0; mf < 4; ++mf)
                ldmx4(a[mf], sa + (wm * 64 + mf * 16 + (lane & 15)) * L_STRIDE + koff);
            uint32_t bfr[4][2];
#pragma unroll
            for (int nh = 0; nh < 2; ++nh) {
                uint32_t t4[4];
                ldmx4(t4, sb + (wn * 32 + nh * 16 + (lane & 15)) * L_STRIDE + koff);
                bfr[nh * 2 + 0][0] = t4[0]; bfr[nh * 2 + 0][1] = t4[2];
                bfr[nh * 2 + 1][0] = t4[1]; bfr[nh * 2 + 1][1] = t4[3];
            }
#pragma unroll
            for (int mf = 0; mf < 4; ++mf)
#pragma unroll
                for (int nf = 0; nf < 4; ++nf)
                    mma16816(acc[mf][nf], a[mf], bfr[nf]);
        }
    }

    // epilogue: bias + (b,s) permute
#pragma unroll
    for (int mf = 0; mf < 4; ++mf) {
        const int mbase = m0 + wm * 64 + mf * 16;
        const int m1 = mbase + (lane >> 2);
        const int m2 = m1 + 8;
        const size_t r1 = (size_t)((m1 & 7) * SEQ + (m1 >> 3)) * VOCAB;
        const size_t r2 = (size_t)((m2 & 7) * SEQ + (m2 >> 3)) * VOCAB;
#pragma unroll
        for (int nf = 0; nf < 4; ++nf) {
            const int n = n0 + wn * 32 + nf * 8 + (lane & 3) * 2;
            const float b0 = bias[n], b1 = bias[n + 1];
            float2 o1 = {acc[mf][nf][0] + b0, acc[mf][nf][1] + b1};
            float2 o2 = {acc[mf][nf][2] + b0, acc[mf][nf][3] + b1};
            *(float2*)(out + r1 + n) = o1;
            *(float2*)(out + r2 + n) = o2;
        }
    }
}

// ---------------- launch ----------------
extern "C" void kernel_launch(void* const* d_in, const int* in_sizes, int n_in,
                              void* d_out, int out_size) {
    const int*   ids_raw  = (const int*)d_in[0];
    const float* W_out    = (const float*)d_in[1];       // [H][V]
    const float* b_out    = (const float*)d_in[2];       // [V]
    const float* Wx       = (const float*)d_in[3];       // [H][4H]
    const float* Wh       = (const float*)d_in[4];       // [H][4H]
    const float* b_lstm   = (const float*)d_in[5];       // [4H]
    float* out            = (float*)d_out;               // [B][S][V]

    void *p_emb, *p_xg;
    cudaGetSymbolAddress(&p_emb, g_emb);
    cudaGetSymbolAddress(&p_xg,  g_xg);

    cudaFuncSetAttribute(lstm_persistent_kernel,
                         cudaFuncAttributeMaxDynamicSharedMemorySize, LP_SMEM_BYTES);
    cudaFuncSetAttribute(logits_mma_kernel,
                         cudaFuncAttributeMaxDynamicSharedMemorySize, L_SMEM);

    // 0) zero h, barrier; decode ids; transpose Wh; split W_out
    init_state_kernel<<<(2 * BATCH * HIDDEN + 255) / 256, 256>>>();
    decode_ids_kernel<<<(MROWS + 255) / 256, 256>>>(ids_raw);
    {
        dim3 tg(HIDDEN / 32, G4 / 32);
        transpose_wh_kernel<<<tg, dim3(32, 8)>>>(Wh);
    }
    {
        dim3 wg(VOCAB / 32, HIDDEN / 32);
        split_wout_kernel<<<wg, dim3(32, 8)>>>(W_out);
    }

    // 1) embedding gather
    gather_kernel<<<(MROWS * HIDDEN) / 256, 256>>>(W_out);

    // 2) x_gates = emb @ Wx + b_lstm
    {
        dim3 grid(G4 / 128, MROWS / 128);
        sgemm128<0><<<grid, 256>>>((const float*)p_emb, Wx, b_lstm, (float*)p_xg,
                                   MROWS, G4, HIDDEN);
    }

    // 3) recurrence: single persistent kernel, 512 steps, global barrier per step
    lstm_persistent_kernel<<<LP_BLOCKS, 256, LP_SMEM_BYTES>>>();

    // 4) split hs to bf16 hi/lo
    split_hs_kernel<<<(MROWS * HIDDEN / 4) / 256, 256>>>();

    // 5) logits = hs @ W_out + b_out via mma.sync bf16 3-product split
    {
        dim3 grid(MROWS / 128, VOCAB / 128);
        logits_mma_kernel<<<grid, 256, L_SMEM>>>(out, b_out);
    }
}

// round 13
// speedup vs baseline: 1.8555x; 1.0850x over previous
#include <cuda_runtime.h>
#include <cuda_bf16.h>
#include <cstdint>
#include <cstddef>

#define VOCAB  32000
#define HIDDEN 1024
#define BATCH  8
#define SEQ    512
#define G4     (4*HIDDEN)       // 4096
#define MROWS  (BATCH*SEQ)      // 4096
#define LP_BLOCKS 128

// ---------------- static device scratch (no allocs allowed) ----------------
__device__ float g_xg [(size_t)MROWS * G4];              // [m][4H]
__device__ float g_hs [(size_t)MROWS * HIDDEN];          // [m][h]
__device__ float g_WhT[(size_t)G4 * HIDDEN];             // [col][k]
__device__ float g_h  [2 * BATCH * HIDDEN];              // double-buffered h
__device__ int   g_ids[MROWS];
__device__ unsigned g_bar;                               // persistent-grid barrier
// bf16 split operands (g_hs_hi/lo double as emb_hi/lo before the recurrence)
__device__ __nv_bfloat16 g_hs_hi[(size_t)MROWS * HIDDEN];   // [m][k]
__device__ __nv_bfloat16 g_hs_lo[(size_t)MROWS * HIDDEN];
__device__ __nv_bfloat16 g_WT_hi[(size_t)VOCAB * HIDDEN];   // [v][k]
__device__ __nv_bfloat16 g_WT_lo[(size_t)VOCAB * HIDDEN];
__device__ __nv_bfloat16 g_WxT_hi[(size_t)G4 * HIDDEN];     // [n][k]
__device__ __nv_bfloat16 g_WxT_lo[(size_t)G4 * HIDDEN];

// ================= helpers =================
#define CP_ASYNC16(dst, src) \
    asm volatile("cp.async.cg.shared.global [%0], [%1], 16;" :: "r"(dst), "l"(src))
#define CP_COMMIT() asm volatile("cp.async.commit_group;" ::: "memory")
#define CP_WAIT(n)  asm volatile("cp.async.wait_group %0;" :: "n"(n) : "memory")

__device__ __forceinline__ uint32_t smem_u32(const void* p) {
    uint32_t a;
    asm("{ .reg .u64 t; cvta.to.shared.u64 t, %1; cvt.u32.u64 %0, t; }" : "=r"(a) : "l"(p));
    return a;
}
__device__ __forceinline__ void ldmx4(uint32_t* r, uint32_t addr) {
    asm volatile("ldmatrix.sync.aligned.m8n8.x4.shared.b16 {%0,%1,%2,%3}, [%4];"
                 : "=r"(r[0]), "=r"(r[1]), "=r"(r[2]), "=r"(r[3]) : "r"(addr));
}
__device__ __forceinline__ void mma16816(float* c, const uint32_t* a, const uint32_t* b) {
    asm volatile("mma.sync.aligned.m16n8k16.row.col.f32.bf16.bf16.f32 "
                 "{%0,%1,%2,%3}, {%4,%5,%6,%7}, {%8,%9}, {%0,%1,%2,%3};"
                 : "+f"(c[0]), "+f"(c[1]), "+f"(c[2]), "+f"(c[3])
                 : "r"(a[0]), "r"(a[1]), "r"(a[2]), "r"(a[3]), "r"(b[0]), "r"(b[1]));
}
__device__ __forceinline__ void bar_arrive() {
    unsigned dummy;
    asm volatile("atom.add.release.gpu.u32 %0, [%1], 1;"
                 : "=r"(dummy) : "l"(&g_bar) : "memory");
}
__device__ __forceinline__ unsigned bar_peek() {
    unsigned v;
    asm volatile("ld.acquire.gpu.u32 %0, [%1];" : "=r"(v) : "l"(&g_bar) : "memory");
    return v;
}

// ---------------- init: zero h, barrier ----------------
__global__ void init_state_kernel() {
    int i = blockIdx.x * 256 + threadIdx.x;
    if (i < 2 * BATCH * HIDDEN) g_h[i] = 0.f;
    if (i == 0)                 g_bar = 0u;
}

// ---------------- dtype-agnostic id decode ----------------
__global__ void decode_ids_kernel(const int* __restrict__ raw) {
    __shared__ int is64;
    if (threadIdx.x == 0) {
        int allzero = 1;
        for (int i = 0; i < 128; ++i)
            if (raw[2 * i + 1] != 0) { allzero = 0; break; }
        is64 = allzero;
    }
    __syncthreads();
    int i = blockIdx.x * 256 + threadIdx.x;
    if (i < MROWS) {
        int v = is64 ? raw[2 * i] : raw[i];
        if (v < 0) v = 0;
        if (v >= VOCAB) v = VOCAB - 1;
        g_ids[i] = v;
    }
}

// ---------------- transpose + split: W[k][n] -> dst_{hi,lo}[n][k] bf16 ----------------
__global__ void transpose_split_kernel(const float* __restrict__ W,
                                       __nv_bfloat16* __restrict__ dhi,
                                       __nv_bfloat16* __restrict__ dlo,
                                       int ncols) {
    __shared__ float t[32][33];
    int v0 = blockIdx.x * 32, k0 = blockIdx.y * 32;
    int x = threadIdx.x, y = threadIdx.y;
#pragma unroll
    for (int i = 0; i < 4; ++i)
        t[y + i * 8][x] = W[(size_t)(k0 + y + i * 8) * ncols + v0 + x];   // t[k][v]
    __syncthreads();
#pragma unroll
    for (int i = 0; i < 4; ++i) {
        float val = t[x][y + i * 8];
        __nv_bfloat16 hi = __float2bfloat16(val);
        size_t o = (size_t)(v0 + y + i * 8) * HIDDEN + k0 + x;
        dhi[o] = hi;
        dlo[o] = __float2bfloat16(val - __bfloat162float(hi));
    }
}

// ---------------- bf16 embedding gather: emb rows = WT rows[ids] ----------------
// grid 4096 blocks (one m-row), 128 threads: 128 x 16B = 2KB = one 1024-bf16 row.
__global__ void gather_emb_bf16_kernel() {
    int m = blockIdx.x;
    int id = g_ids[(m & 7) * SEQ + (m >> 3)];
    const uint4* sh = (const uint4*)(g_WT_hi + (size_t)id * HIDDEN);
    const uint4* sl = (const uint4*)(g_WT_lo + (size_t)id * HIDDEN);
    uint4* dh = (uint4*)(g_hs_hi + (size_t)m * HIDDEN);
    uint4* dl = (uint4*)(g_hs_lo + (size_t)m * HIDDEN);
    dh[threadIdx.x] = sh[threadIdx.x];
    dl[threadIdx.x] = sl[threadIdx.x];
}

// ---------------- split hs -> bf16 hi/lo ----------------
__global__ void split_hs_kernel() {
    int i = (blockIdx.x * 256 + threadIdx.x) * 4;
    float4 v = *(const float4*)&g_hs[i];
    float vv[4] = {v.x, v.y, v.z, v.w};
#pragma unroll
    for (int j = 0; j < 4; ++j) {
        __nv_bfloat16 hi = __float2bfloat16(vv[j]);
        g_hs_hi[i + j] = hi;
        g_hs_lo[i + j] = __float2bfloat16(vv[j] - __bfloat162float(hi));
    }
}

// ---------------- Wh transpose ----------------
__global__ void transpose_wh_kernel(const float* __restrict__ Wh) {
    __shared__ float t[32][33];
    int bx = blockIdx.x, by = blockIdx.y;
    int x = threadIdx.x, y = threadIdx.y;
#pragma unroll
    for (int i = 0; i < 4; ++i)
        t[y + i * 8][x] = Wh[(size_t)(bx * 32 + y + i * 8) * G4 + by * 32 + x];
    __syncthreads();
#pragma unroll
    for (int i = 0; i < 4; ++i)
        g_WhT[(size_t)(by * 32 + y + i * 8) * HIDDEN + bx * 32 + x] = t[x][y + i * 8];
}

// ================= persistent LSTM recurrence (register-resident weights) ========
// 128 blocks x 256 threads. Warp = jl, lanes = contiguous float4 k-chunks.
// Wh weights live in 128 registers/thread for all 512 steps (step-invariant).
// smem: h_s 8192 | part 8448 | gsum 256 floats = 67.6 KB
#define LP_SMEM_BYTES ((8192 + 8448 + 256) * 4)
__global__ __launch_bounds__(256, 1) void lstm_persistent_kernel() {
    extern __shared__ float sm[];
    float* h_s  = sm;              // [b][k]      8 x 1024
    float* part = sm + 8192;       // [combo][33] 256 x 33
    float* gsum = sm + 16640;      // [256]

    const int tid = threadIdx.x;
    const int j0  = blockIdx.x * 8;
    const int wjl = tid >> 5;       // warp index = jl
    const int ln  = tid & 31;

    // weights into registers: wreg[c][g] = WhT[g*1024 + j0+wjl][c*128 + ln*4 ..+3]
    float4 wreg[8][4];
#pragma unroll
    for (int c = 0; c < 8; ++c)
#pragma unroll
        for (int g = 0; g < 4; ++g)
            wreg[c][g] = *(const float4*)&g_WhT[
                (size_t)(g * HIDDEN + j0 + wjl) * HIDDEN + c * 128 + ln * 4];

    // reduce mapping: combo = tid -> (rjl, rg, rb)
    const int rjl = tid >> 5, rg = (tid >> 3) & 3, rb = tid & 7;
    const int xg_col = rg * HIDDEN + j0 + rjl;
    // finalize mapping (tid < 64): (jl3, b3); c state lives here across steps
    float c_reg = 0.f;
    const int jl3 = tid >> 3, b3 = tid & 7;

    __syncthreads();

    for (int t = 0; t < SEQ; ++t) {
        float xg_val = __ldg(&g_xg[((size_t)t * 8 + rb) * G4 + xg_col]);

        const float* hin = g_h + (t & 1) * (BATCH * HIDDEN);
        for (int i = tid * 4; i < BATCH * HIDDEN; i += 1024)
            *(float4*)&h_s[i] = __ldcg((const float4*)(hin + i));
        __syncthreads();

        float acc[4][8];
#pragma unroll
        for (int g = 0; g < 4; ++g)
#pragma unroll
            for (int b = 0; b < 8; ++b) acc[g][b] = 0.f;

#pragma unroll
        for (int c = 0; c < 8; ++c) {
            const int k = c * 128 + ln * 4;
            const float4 w0 = wreg[c][0];
            const float4 w1 = wreg[c][1];
            const float4 w2 = wreg[c][2];
            const float4 w3 = wreg[c][3];
#pragma unroll
            for (int b = 0; b < 8; ++b) {
                float4 hv = *(const float4*)&h_s[b * 1024 + k];
                acc[0][b] = fmaf(w0.x, hv.x, acc[0][b]);
                acc[0][b] = fmaf(w0.y, hv.y, acc[0][b]);
                acc[0][b] = fmaf(w0.z, hv.z, acc[0][b]);
                acc[0][b] = fmaf(w0.w, hv.w, acc[0][b]);
                acc[1][b] = fmaf(w1.x, hv.x, acc[1][b]);
                acc[1][b] = fmaf(w1.y, hv.y, acc[1][b]);
                acc[1][b] = fmaf(w1.z, hv.z, acc[1][b]);
                acc[1][b] = fmaf(w1.w, hv.w, acc[1][b]);
                acc[2][b] = fmaf(w2.x, hv.x, acc[2][b]);
                acc[2][b] = fmaf(w2.y, hv.y, acc[2][b]);
                acc[2][b] = fmaf(w2.z, hv.z, acc[2][b]);
                acc[2][b] = fmaf(w2.w, hv.w, acc[2][b]);
                acc[3][b] = fmaf(w3.x, hv.x, acc[3][b]);
                acc[3][b] = fmaf(w3.y, hv.y, acc[3][b]);
                acc[3][b] = fmaf(w3.z, hv.z, acc[3][b]);
                acc[3][b] = fmaf(w3.w, hv.w, acc[3][b]);
            }
        }
#pragma unroll
        for (int g = 0; g < 4; ++g)
#pragma unroll
            for (int b = 0; b < 8; ++b)
                part[((wjl * 4 + g) * 8 + b) * 33 + ln] = acc[g][b];
        __syncthreads();

        {
            float s = 0.f;
            const float* pr = part + tid * 33;
#pragma unroll
            for (int i = 0; i < 32; ++i) s += pr[i];
            gsum[tid] = s + xg_val;
        }
        __syncthreads();

        if (tid < 64) {
            float gv0 = gsum[jl3 * 32 + 0 + b3];
            float gv1 = gsum[jl3 * 32 + 8 + b3];
            float gv2 = gsum[jl3 * 32 + 16 + b3];
            float gv3 = gsum[jl3 * 32 + 24 + b3];
            float i_ = 1.f / (1.f + expf(-gv0));
            float f_ = 1.f / (1.f + expf(-gv1));
            float gg = tanhf(gv2);
            float o_ = 1.f / (1.f + expf(-gv3));
            c_reg = f_ * c_reg + i_ * gg;
            float hn = o_ * tanhf(c_reg);
            int j = j0 + jl3;
            g_h[((t + 1) & 1) * (BATCH * HIDDEN) + b3 * HIDDEN + j] = hn;
            g_hs[((size_t)t * 8 + b3) * HIDDEN + j] = hn;
        }
        __syncthreads();
        if (tid == 0) {
            bar_arrive();
            const unsigned target = (unsigned)LP_BLOCKS * (unsigned)(t + 1);
            while (bar_peek() < target) __nanosleep(32);
        }
        __syncthreads();
    }
}

// ================= mma.sync bf16-split GEMM (4-stage, 1 sync/iter) =================
// CTA tile 128x128, 8 warps (2 M x 4 N), warp tile 64x32, m16n8k16 HMMA.
// 3 products: Ahi*Bhi + Ahi*Blo + Alo*Bhi over K=1024, BK=32, cp.async 4-stage.
// PERM=1: out row = (m&7)*SEQ + (m>>3) (logits). PERM=0: out row = m (x_gates).
#define L_STRIDE  80
#define L_AB      (128 * L_STRIDE)
#define L_STAGE   (2 * L_AB)
#define L_NIT     96
#define L_SMEM    (4 * L_STAGE)            // 81920 bytes

template <int PERM>
__global__ __launch_bounds__(256, 2) void mma_gemm_kernel(
        const __nv_bfloat16* __restrict__ Ahi, const __nv_bfloat16* __restrict__ Alo,
        const __nv_bfloat16* __restrict__ Bhi, const __nv_bfloat16* __restrict__ Blo,
        const float* __restrict__ bias, float* __restrict__ out, int Ntot) {
    extern __shared__ char lsm[];
    const uint32_t sbase = smem_u32(lsm);

    const int tid  = threadIdx.x;
    const int lane = tid & 31;
    const int wid  = tid >> 5;
    const int wm   = wid >> 2;
    const int wn   = wid & 3;
    const int m0   = blockIdx.x * 128;
    const int n0   = blockIdx.y * 128;

    const int lrow = tid >> 2;
    const int lch  = tid & 3;

    float acc[4][4][4];
#pragma unroll
    for (int i = 0; i < 4; ++i)
#pragma unroll
        for (int j = 0; j < 4; ++j)
#pragma unroll
            for (int k = 0; k < 4; ++k) acc[i][j][k] = 0.f;

    auto load_stage = [&](int it, int s) {
        const int p  = it >> 5;
        const int k0 = (it & 31) * 32;
        const __nv_bfloat16* Asrc = (p < 2) ? Ahi : Alo;
        const __nv_bfloat16* Bsrc = (p == 1) ? Blo : Bhi;
        uint32_t sa = sbase + s * L_STAGE;
        uint32_t sb = sa + L_AB;
#pragma unroll
        for (int rr = 0; rr < 128; rr += 64) {
            const __nv_bfloat16* srcA = Asrc + (size_t)(m0 + lrow + rr) * HIDDEN + k0 + lch * 8;
            CP_ASYNC16(sa + (lrow + rr) * L_STRIDE + lch * 16, srcA);
            const __nv_bfloat16* srcB = Bsrc + (size_t)(n0 + lrow + rr) * HIDDEN + k0 + lch * 8;
            CP_ASYNC16(sb + (lrow + rr) * L_STRIDE + lch * 16, srcB);
        }
        CP_COMMIT();
    };

    load_stage(0, 0);
    load_stage(1, 1);

    for (int it = 0; it < L_NIT; ++it) {
        if (it + 2 < L_NIT) {
            load_stage(it + 2, (it + 2) & 3);
            CP_WAIT(2);
        } else {
            CP_WAIT(0);
        }
        __syncthreads();

        uint32_t sa = sbase + (it & 3) * L_STAGE;
        uint32_t sb = sa + L_AB;
#pragma unroll
        for (int k16 = 0; k16 < 2; ++k16) {
            const uint32_t koff = k16 * 32 + (lane >> 4) * 16;
            uint32_t a[4][4];
#pragma unroll
            for (int mf = 0; mf < 4; ++mf)
                ldmx4(a[mf], sa + (wm * 64 + mf * 16 + (lane & 15)) * L_STRIDE + koff);
            uint32_t bfr[4][2];
#pragma unroll
            for (int nh = 0; nh < 2; ++nh) {
                uint32_t t4[4];
                ldmx4(t4, sb + (wn * 32 + nh * 16 + (lane & 15)) * L_STRIDE + koff);
                bfr[nh * 2 + 0][0] = t4[0]; bfr[nh * 2 + 0][1] = t4[2];
                bfr[nh * 2 + 1][0] = t4[1]; bfr[nh * 2 + 1][1] = t4[3];
            }
#pragma unroll
            for (int mf = 0; mf < 4; ++mf)
#pragma unroll
                for (int nf = 0; nf < 4; ++nf)
                    mma16816(acc[mf][nf], a[mf], bfr[nf]);
        }
    }

    // epilogue: bias + optional (b,s) permute
#pragma unroll
    for (int mf = 0; mf < 4; ++mf) {
        const int mbase = m0 + wm * 64 + mf * 16;
        const int m1 = mbase + (lane >> 2);
        const int m2 = m1 + 8;
        const size_t r1 = (PERM ? (size_t)((m1 & 7) * SEQ + (m1 >> 3)) : (size_t)m1) * Ntot;
        const size_t r2 = (PERM ? (size_t)((m2 & 7) * SEQ + (m2 >> 3)) : (size_t)m2) * Ntot;
#pragma unroll
        for (int nf = 0; nf < 4; ++nf) {
            const int n = n0 + wn * 32 + nf * 8 + (lane & 3) * 2;
            const float b0 = bias[n], b1 = bias[n + 1];
            float2 o1 = {acc[mf][nf][0] + b0, acc[mf][nf][1] + b1};
            float2 o2 = {acc[mf][nf][2] + b0, acc[mf][nf][3] + b1};
            *(float2*)(out + r1 + n) = o1;
            *(float2*)(out + r2 + n) = o2;
        }
    }
}

// ---------------- launch ----------------
extern "C" void kernel_launch(void* const* d_in, const int* in_sizes, int n_in,
                              void* d_out, int out_size) {
    const int*   ids_raw  = (const int*)d_in[0];
    const float* W_out    = (const float*)d_in[1];       // [H][V]
    const float* b_out    = (const float*)d_in[2];       // [V]
    const float* Wx       = (const float*)d_in[3];       // [H][4H]
    const float* Wh       = (const float*)d_in[4];       // [H][4H]
    const float* b_lstm   = (const float*)d_in[5];       // [4H]
    float* out            = (float*)d_out;               // [B][S][V]

    void *p_xg, *p_hshi, *p_hslo, *p_wthi, *p_wtlo, *p_wxhi, *p_wxlo;
    cudaGetSymbolAddress(&p_xg,   g_xg);
    cudaGetSymbolAddress(&p_hshi, g_hs_hi);
    cudaGetSymbolAddress(&p_hslo, g_hs_lo);
    cudaGetSymbolAddress(&p_wthi, g_WT_hi);
    cudaGetSymbolAddress(&p_wtlo, g_WT_lo);
    cudaGetSymbolAddress(&p_wxhi, g_WxT_hi);
    cudaGetSymbolAddress(&p_wxlo, g_WxT_lo);

    cudaFuncSetAttribute(lstm_persistent_kernel,
                         cudaFuncAttributeMaxDynamicSharedMemorySize, LP_SMEM_BYTES);
    cudaFuncSetAttribute(mma_gemm_kernel<0>,
                         cudaFuncAttributeMaxDynamicSharedMemorySize, L_SMEM);
    cudaFuncSetAttribute(mma_gemm_kernel<1>,
                         cudaFuncAttributeMaxDynamicSharedMemorySize, L_SMEM);

    // 0) zero h/barrier; decode ids; transpose Wh; split W_out and Wx
    init_state_kernel<<<(2 * BATCH * HIDDEN + 255) / 256, 256>>>();
    decode_ids_kernel<<<(MROWS + 255) / 256, 256>>>(ids_raw);
    {
        dim3 tg(HIDDEN / 32, G4 / 32);
        transpose_wh_kernel<<<tg, dim3(32, 8)>>>(Wh);
    }
    transpose_split_kernel<<<dim3(VOCAB / 32, HIDDEN / 32), dim3(32, 8)>>>(
        W_out, (__nv_bfloat16*)p_wthi, (__nv_bfloat16*)p_wtlo, VOCAB);
    transpose_split_kernel<<<dim3(G4 / 32, HIDDEN / 32), dim3(32, 8)>>>(
        Wx, (__nv_bfloat16*)p_wxhi, (__nv_bfloat16*)p_wxlo, G4);

    // 1) bf16 embedding gather (emb rows = WT rows[ids]) into g_hs_hi/lo
    gather_emb_bf16_kernel<<<MROWS, 128>>>();

    // 2) x_gates = emb @ Wx + b_lstm via bf16 3-product HMMA (no permute)
    mma_gemm_kernel<0><<<dim3(MROWS / 128, G4 / 128), 256, L_SMEM>>>(
        (const __nv_bfloat16*)p_hshi, (const __nv_bfloat16*)p_hslo,
        (const __nv_bfloat16*)p_wxhi, (const __nv_bfloat16*)p_wxlo,
        b_lstm, (float*)p_xg, G4);

    // 3) recurrence: persistent kernel, 512 steps, grid barrier per step
    lstm_persistent_kernel<<<LP_BLOCKS, 256, LP_SMEM_BYTES>>>();

    // 4) split hs to bf16 hi/lo (overwrites emb buffers — emb no longer needed)
    split_hs_kernel<<<(MROWS * HIDDEN / 4) / 256, 256>>>();

    // 5) logits = hs @ W_out + b_out via bf16 3-product HMMA (with (b,s) permute)
    mma_gemm_kernel<1><<<dim3(MROWS / 128, VOCAB / 128), 256, L_SMEM>>>(
        (const __nv_bfloat16*)p_hshi, (const __nv_bfloat16*)p_hslo,
        (const __nv_bfloat16*)p_wthi, (const __nv_bfloat16*)p_wtlo,
        b_out, out, VOCAB);
}

// round 14
// speedup vs baseline: 1.9525x; 1.0522x over previous
#include <cuda_runtime.h>
#include <cuda_bf16.h>
#include <cstdint>
#include <cstddef>

#define VOCAB  32000
#define HIDDEN 1024
#define BATCH  8
#define SEQ    512
#define G4     (4*HIDDEN)       // 4096
#define MROWS  (BATCH*SEQ)      // 4096
#define LP_BLOCKS 128

// ---------------- static device scratch (no allocs allowed) ----------------
__device__ float g_xg [(size_t)MROWS * G4];              // [m][4H]
__device__ float g_hs [(size_t)MROWS * HIDDEN];          // [m][h]
__device__ float g_WhT[(size_t)G4 * HIDDEN];             // [col][k]
__device__ float g_h  [2 * BATCH * HIDDEN];              // double-buffered h
__device__ int   g_ids[MROWS];
__device__ unsigned g_bar;                               // persistent-grid barrier
// bf16 split operands (g_hs_hi/lo double as emb_hi/lo before the recurrence)
__device__ __nv_bfloat16 g_hs_hi[(size_t)MROWS * HIDDEN];   // [m][k]
__device__ __nv_bfloat16 g_hs_lo[(size_t)MROWS * HIDDEN];
__device__ __nv_bfloat16 g_WT_hi[(size_t)VOCAB * HIDDEN];   // [v][k]
__device__ __nv_bfloat16 g_WT_lo[(size_t)VOCAB * HIDDEN];
__device__ __nv_bfloat16 g_WxT_hi[(size_t)G4 * HIDDEN];     // [n][k]
__device__ __nv_bfloat16 g_WxT_lo[(size_t)G4 * HIDDEN];

// ================= helpers =================
#define CP_ASYNC16(dst, src) \
    asm volatile("cp.async.cg.shared.global [%0], [%1], 16;" :: "r"(dst), "l"(src))
#define CP_COMMIT() asm volatile("cp.async.commit_group;" ::: "memory")
#define CP_WAIT(n)  asm volatile("cp.async.wait_group %0;" :: "n"(n) : "memory")

__device__ __forceinline__ uint32_t smem_u32(const void* p) {
    uint32_t a;
    asm("{ .reg .u64 t; cvta.to.shared.u64 t, %1; cvt.u32.u64 %0, t; }" : "=r"(a) : "l"(p));
    return a;
}
__device__ __forceinline__ void ldmx4(uint32_t* r, uint32_t addr) {
    asm volatile("ldmatrix.sync.aligned.m8n8.x4.shared.b16 {%0,%1,%2,%3}, [%4];"
                 : "=r"(r[0]), "=r"(r[1]), "=r"(r[2]), "=r"(r[3]) : "r"(addr));
}
__device__ __forceinline__ void mma16816(float* c, const uint32_t* a, const uint32_t* b) {
    asm volatile("mma.sync.aligned.m16n8k16.row.col.f32.bf16.bf16.f32 "
                 "{%0,%1,%2,%3}, {%4,%5,%6,%7}, {%8,%9}, {%0,%1,%2,%3};"
                 : "+f"(c[0]), "+f"(c[1]), "+f"(c[2]), "+f"(c[3])
                 : "r"(a[0]), "r"(a[1]), "r"(a[2]), "r"(a[3]), "r"(b[0]), "r"(b[1]));
}
__device__ __forceinline__ void bar_arrive() {
    unsigned dummy;
    asm volatile("atom.add.release.gpu.u32 %0, [%1], 1;"
                 : "=r"(dummy) : "l"(&g_bar) : "memory");
}
__device__ __forceinline__ unsigned bar_peek() {
    unsigned v;
    asm volatile("ld.acquire.gpu.u32 %0, [%1];" : "=r"(v) : "l"(&g_bar) : "memory");
    return v;
}

// ---------------- init: zero h, barrier ----------------
__global__ void init_state_kernel() {
    int i = blockIdx.x * 256 + threadIdx.x;
    if (i < 2 * BATCH * HIDDEN) g_h[i] = 0.f;
    if (i == 0)                 g_bar = 0u;
}

// ---------------- dtype-agnostic id decode ----------------
__global__ void decode_ids_kernel(const int* __restrict__ raw) {
    __shared__ int is64;
    if (threadIdx.x == 0) {
        int allzero = 1;
        for (int i = 0; i < 128; ++i)
            if (raw[2 * i + 1] != 0) { allzero = 0; break; }
        is64 = allzero;
    }
    __syncthreads();
    int i = blockIdx.x * 256 + threadIdx.x;
    if (i < MROWS) {
        int v = is64 ? raw[2 * i] : raw[i];
        if (v < 0) v = 0;
        if (v >= VOCAB) v = VOCAB - 1;
        g_ids[i] = v;
    }
}

// ---------------- transpose + split: W[k][n] -> dst_{hi,lo}[n][k] bf16 ----------------
__global__ void transpose_split_kernel(const float* __restrict__ W,
                                       __nv_bfloat16* __restrict__ dhi,
                                       __nv_bfloat16* __restrict__ dlo,
                                       int ncols) {
    __shared__ float t[32][33];
    int v0 = blockIdx.x * 32, k0 = blockIdx.y * 32;
    int x = threadIdx.x, y = threadIdx.y;
#pragma unroll
    for (int i = 0; i < 4; ++i)
        t[y + i * 8][x] = W[(size_t)(k0 + y + i * 8) * ncols + v0 + x];   // t[k][v]
    __syncthreads();
#pragma unroll
    for (int i = 0; i < 4; ++i) {
        float val = t[x][y + i * 8];
        __nv_bfloat16 hi = __float2bfloat16(val);
        size_t o = (size_t)(v0 + y + i * 8) * HIDDEN + k0 + x;
        dhi[o] = hi;
        dlo[o] = __float2bfloat16(val - __bfloat162float(hi));
    }
}

// ---------------- bf16 embedding gather: emb rows = WT rows[ids] ----------------
__global__ void gather_emb_bf16_kernel() {
    int m = blockIdx.x;
    int id = g_ids[(m & 7) * SEQ + (m >> 3)];
    const uint4* sh = (const uint4*)(g_WT_hi + (size_t)id * HIDDEN);
    const uint4* sl = (const uint4*)(g_WT_lo + (size_t)id * HIDDEN);
    uint4* dh = (uint4*)(g_hs_hi + (size_t)m * HIDDEN);
    uint4* dl = (uint4*)(g_hs_lo + (size_t)m * HIDDEN);
    dh[threadIdx.x] = sh[threadIdx.x];
    dl[threadIdx.x] = sl[threadIdx.x];
}

// ---------------- split hs -> bf16 hi/lo ----------------
__global__ void split_hs_kernel() {
    int i = (blockIdx.x * 256 + threadIdx.x) * 4;
    float4 v = *(const float4*)&g_hs[i];
    float vv[4] = {v.x, v.y, v.z, v.w};
#pragma unroll
    for (int j = 0; j < 4; ++j) {
        __nv_bfloat16 hi = __float2bfloat16(vv[j]);
        g_hs_hi[i + j] = hi;
        g_hs_lo[i + j] = __float2bfloat16(vv[j] - __bfloat162float(hi));
    }
}

// ---------------- Wh transpose ----------------
__global__ void transpose_wh_kernel(const float* __restrict__ Wh) {
    __shared__ float t[32][33];
    int bx = blockIdx.x, by = blockIdx.y;
    int x = threadIdx.x, y = threadIdx.y;
#pragma unroll
    for (int i = 0; i < 4; ++i)
        t[y + i * 8][x] = Wh[(size_t)(bx * 32 + y + i * 8) * G4 + by * 32 + x];
    __syncthreads();
#pragma unroll
    for (int i = 0; i < 4; ++i)
        g_WhT[(size_t)(by * 32 + y + i * 8) * HIDDEN + bx * 32 + x] = t[x][y + i * 8];
}

// ================= persistent LSTM recurrence (register-resident weights) ========
#define LP_SMEM_BYTES ((8192 + 8448 + 256) * 4)
__global__ __launch_bounds__(256, 1) void lstm_persistent_kernel() {
    extern __shared__ float sm[];
    float* h_s  = sm;              // [b][k]      8 x 1024
    float* part = sm + 8192;       // [combo][33] 256 x 33
    float* gsum = sm + 16640;      // [256]

    const int tid = threadIdx.x;
    const int j0  = blockIdx.x * 8;
    const int wjl = tid >> 5;
    const int ln  = tid & 31;

    float4 wreg[8][4];
#pragma unroll
    for (int c = 0; c < 8; ++c)
#pragma unroll
        for (int g = 0; g < 4; ++g)
            wreg[c][g] = *(const float4*)&g_WhT[
                (size_t)(g * HIDDEN + j0 + wjl) * HIDDEN + c * 128 + ln * 4];

    const int rjl = tid >> 5, rg = (tid >> 3) & 3, rb = tid & 7;
    const int xg_col = rg * HIDDEN + j0 + rjl;
    float c_reg = 0.f;
    const int jl3 = tid >> 3, b3 = tid & 7;

    __syncthreads();

    for (int t = 0; t < SEQ; ++t) {
        float xg_val = __ldg(&g_xg[((size_t)t * 8 + rb) * G4 + xg_col]);

        const float* hin = g_h + (t & 1) * (BATCH * HIDDEN);
        for (int i = tid * 4; i < BATCH * HIDDEN; i += 1024)
            *(float4*)&h_s[i] = __ldcg((const float4*)(hin + i));
        __syncthreads();

        float acc[4][8];
#pragma unroll
        for (int g = 0; g < 4; ++g)
#pragma unroll
            for (int b = 0; b < 8; ++b) acc[g][b] = 0.f;

#pragma unroll
        for (int c = 0; c < 8; ++c) {
            const int k = c * 128 + ln * 4;
            const float4 w0 = wreg[c][0];
            const float4 w1 = wreg[c][1];
            const float4 w2 = wreg[c][2];
            const float4 w3 = wreg[c][3];
#pragma unroll
            for (int b = 0; b < 8; ++b) {
                float4 hv = *(const float4*)&h_s[b * 1024 + k];
                acc[0][b] = fmaf(w0.x, hv.x, acc[0][b]);
                acc[0][b] = fmaf(w0.y, hv.y, acc[0][b]);
                acc[0][b] = fmaf(w0.z, hv.z, acc[0][b]);
                acc[0][b] = fmaf(w0.w, hv.w, acc[0][b]);
                acc[1][b] = fmaf(w1.x, hv.x, acc[1][b]);
                acc[1][b] = fmaf(w1.y, hv.y, acc[1][b]);
                acc[1][b] = fmaf(w1.z, hv.z, acc[1][b]);
                acc[1][b] = fmaf(w1.w, hv.w, acc[1][b]);
                acc[2][b] = fmaf(w2.x, hv.x, acc[2][b]);
                acc[2][b] = fmaf(w2.y, hv.y, acc[2][b]);
                acc[2][b] = fmaf(w2.z, hv.z, acc[2][b]);
                acc[2][b] = fmaf(w2.w, hv.w, acc[2][b]);
                acc[3][b] = fmaf(w3.x, hv.x, acc[3][b]);
                acc[3][b] = fmaf(w3.y, hv.y, acc[3][b]);
                acc[3][b] = fmaf(w3.z, hv.z, acc[3][b]);
                acc[3][b] = fmaf(w3.w, hv.w, acc[3][b]);
            }
        }
#pragma unroll
        for (int g = 0; g < 4; ++g)
#pragma unroll
            for (int b = 0; b < 8; ++b)
                part[((wjl * 4 + g) * 8 + b) * 33 + ln] = acc[g][b];
        __syncthreads();

        {
            float s = 0.f;
            const float* pr = part + tid * 33;
#pragma unroll
            for (int i = 0; i < 32; ++i) s += pr[i];
            gsum[tid] = s + xg_val;
        }
        __syncthreads();

        if (tid < 64) {
            float gv0 = gsum[jl3 * 32 + 0 + b3];
            float gv1 = gsum[jl3 * 32 + 8 + b3];
            float gv2 = gsum[jl3 * 32 + 16 + b3];
            float gv3 = gsum[jl3 * 32 + 24 + b3];
            float i_ = 1.f / (1.f + expf(-gv0));
            float f_ = 1.f / (1.f + expf(-gv1));
            float gg = tanhf(gv2);
            float o_ = 1.f / (1.f + expf(-gv3));
            c_reg = f_ * c_reg + i_ * gg;
            float hn = o_ * tanhf(c_reg);
            int j = j0 + jl3;
            g_h[((t + 1) & 1) * (BATCH * HIDDEN) + b3 * HIDDEN + j] = hn;
            g_hs[((size_t)t * 8 + b3) * HIDDEN + j] = hn;
        }
        __syncthreads();
        if (tid == 0) {
            bar_arrive();
            const unsigned target = (unsigned)LP_BLOCKS * (unsigned)(t + 1);
            while (bar_peek() < target) __nanosleep(32);
        }
        __syncthreads();
    }
}

// ================= fused 3-product bf16-split HMMA GEMM =================
// CTA tile 128x128, 8 warps (2 M x 4 N). Per 32-wide k-chunk: load ALL FOUR
// tiles {Ahi, Alo, Bhi, Blo} into one 40KB stage, then issue all 3 products
// (Ahi*Bhi + Ahi*Blo + Alo*Bhi = 48 MMAs) from one smem residency.
// 32 chunks, 2-stage cp.async, 2 syncs/chunk, 2 CTAs/SM.
#define L_STRIDE  80
#define L_AB      (128 * L_STRIDE)         // 10240 B per tile
#define L_STAGE   (4 * L_AB)               // Ahi|Alo|Bhi|Blo = 40960 B
#define L_SMEM    (2 * L_STAGE)            // 81920 B

template <int PERM>
__global__ __launch_bounds__(256, 2) void mma_gemm_kernel(
        const __nv_bfloat16* __restrict__ Ahi, const __nv_bfloat16* __restrict__ Alo,
        const __nv_bfloat16* __restrict__ Bhi, const __nv_bfloat16* __restrict__ Blo,
        const float* __restrict__ bias, float* __restrict__ out, int Ntot) {
    extern __shared__ char lsm[];
    const uint32_t sbase = smem_u32(lsm);

    const int tid  = threadIdx.x;
    const int lane = tid & 31;
    const int wid  = tid >> 5;
    const int wm   = wid >> 2;
    const int wn   = wid & 3;
    const int m0   = blockIdx.x * 128;
    const int n0   = blockIdx.y * 128;

    const int lrow = tid >> 2;             // 0..63
    const int lch  = tid & 3;

    float acc[4][4][4];
#pragma unroll
    for (int i = 0; i < 4; ++i)
#pragma unroll
        for (int j = 0; j < 4; ++j)
#pragma unroll
            for (int k = 0; k < 4; ++k) acc[i][j][k] = 0.f;

    // load one 32-wide k-chunk: all four tiles into stage s
    auto load_chunk = [&](int c, int s) {
        const int k0 = c * 32;
        uint32_t sb0 = sbase + s * L_STAGE;
#pragma unroll
        for (int rr = 0; rr < 128; rr += 64) {
            const size_t aoff = (size_t)(m0 + lrow + rr) * HIDDEN + k0 + lch * 8;
            const size_t boff = (size_t)(n0 + lrow + rr) * HIDDEN + k0 + lch * 8;
            const uint32_t doff = (lrow + rr) * L_STRIDE + lch * 16;
            CP_ASYNC16(sb0 + 0 * L_AB + doff, Ahi + aoff);
            CP_ASYNC16(sb0 + 1 * L_AB + doff, Alo + aoff);
            CP_ASYNC16(sb0 + 2 * L_AB + doff, Bhi + boff);
            CP_ASYNC16(sb0 + 3 * L_AB + doff, Blo + boff);
        }
        CP_COMMIT();
    };

    load_chunk(0, 0);

    for (int c = 0; c < 32; ++c) {
        if (c + 1 < 32) {
            load_chunk(c + 1, (c + 1) & 1);
            CP_WAIT(1);
        } else {
            CP_WAIT(0);
        }
        __syncthreads();

        const uint32_t st = sbase + (c & 1) * L_STAGE;
#pragma unroll
        for (int k16 = 0; k16 < 2; ++k16) {
            const uint32_t koff = k16 * 32 + (lane >> 4) * 16;
            const uint32_t arow = (wm * 64 + (lane & 15)) * L_STRIDE + koff;
            const uint32_t brow = (wn * 32 + (lane & 15)) * L_STRIDE + koff;

            uint32_t a[4][4];
#pragma unroll
            for (int mf = 0; mf < 4; ++mf)                     // A hi fragments
                ldmx4(a[mf], st + arow + mf * 16 * L_STRIDE);

            uint32_t bh[4][2], bl[4][2];
#pragma unroll
            for (int nh = 0; nh < 2; ++nh) {
                uint32_t t4[4];
                ldmx4(t4, st + 2 * L_AB + brow + nh * 16 * L_STRIDE);   // B hi
                bh[nh * 2 + 0][0] = t4[0]; bh[nh * 2 + 0][1] = t4[2];
                bh[nh * 2 + 1][0] = t4[1]; bh[nh * 2 + 1][1] = t4[3];
                ldmx4(t4, st + 3 * L_AB + brow + nh * 16 * L_STRIDE);   // B lo
                bl[nh * 2 + 0][0] = t4[0]; bl[nh * 2 + 0][1] = t4[2];
                bl[nh * 2 + 1][0] = t4[1]; bl[nh * 2 + 1][1] = t4[3];
            }

#pragma unroll
            for (int mf = 0; mf < 4; ++mf)
#pragma unroll
                for (int nf = 0; nf < 4; ++nf) {
                    mma16816(acc[mf][nf], a[mf], bh[nf]);      // Ahi*Bhi
                    mma16816(acc[mf][nf], a[mf], bl[nf]);      // Ahi*Blo
                }

#pragma unroll
            for (int mf = 0; mf < 4; ++mf)                     // A lo (reuse regs)
                ldmx4(a[mf], st + 1 * L_AB + arow + mf * 16 * L_STRIDE);
#pragma unroll
            for (int mf = 0; mf < 4; ++mf)
#pragma unroll
                for (int nf = 0; nf < 4; ++nf)
                    mma16816(acc[mf][nf], a[mf], bh[nf]);      // Alo*Bhi
        }
        __syncthreads();
    }

    // epilogue: bias + optional (b,s) permute
#pragma unroll
    for (int mf = 0; mf < 4; ++mf) {
        const int mbase = m0 + wm * 64 + mf * 16;
        const int m1 = mbase + (lane >> 2);
        const int m2 = m1 + 8;
        const size_t r1 = (PERM ? (size_t)((m1 & 7) * SEQ + (m1 >> 3)) : (size_t)m1) * Ntot;
        const size_t r2 = (PERM ? (size_t)((m2 & 7) * SEQ + (m2 >> 3)) : (size_t)m2) * Ntot;
#pragma unroll
        for (int nf = 0; nf < 4; ++nf) {
            const int n = n0 + wn * 32 + nf * 8 + (lane & 3) * 2;
            const float b0 = bias[n], b1 = bias[n + 1];
            float2 o1 = {acc[mf][nf][0] + b0, acc[mf][nf][1] + b1};
            float2 o2 = {acc[mf][nf][2] + b0, acc[mf][nf][3] + b1};
            *(float2*)(out + r1 + n) = o1;
            *(float2*)(out + r2 + n) = o2;
        }
    }
}

// ---------------- launch ----------------
extern "C" void kernel_launch(void* const* d_in, const int* in_sizes, int n_in,
                              void* d_out, int out_size) {
    const int*   ids_raw  = (const int*)d_in[0];
    const float* W_out    = (const float*)d_in[1];       // [H][V]
    const float* b_out    = (const float*)d_in[2];       // [V]
    const float* Wx       = (const float*)d_in[3];       // [H][4H]
    const float* Wh       = (const float*)d_in[4];       // [H][4H]
    const float* b_lstm   = (const float*)d_in[5];       // [4H]
    float* out            = (float*)d_out;               // [B][S][V]

    void *p_xg, *p_hshi, *p_hslo, *p_wthi, *p_wtlo, *p_wxhi, *p_wxlo;
    cudaGetSymbolAddress(&p_xg,   g_xg);
    cudaGetSymbolAddress(&p_hshi, g_hs_hi);
    cudaGetSymbolAddress(&p_hslo, g_hs_lo);
    cudaGetSymbolAddress(&p_wthi, g_WT_hi);
    cudaGetSymbolAddress(&p_wtlo, g_WT_lo);
    cudaGetSymbolAddress(&p_wxhi, g_WxT_hi);
    cudaGetSymbolAddress(&p_wxlo, g_WxT_lo);

    cudaFuncSetAttribute(lstm_persistent_kernel,
                         cudaFuncAttributeMaxDynamicSharedMemorySize, LP_SMEM_BYTES);
    cudaFuncSetAttribute(mma_gemm_kernel<0>,
                         cudaFuncAttributeMaxDynamicSharedMemorySize, L_SMEM);
    cudaFuncSetAttribute(mma_gemm_kernel<1>,
                         cudaFuncAttributeMaxDynamicSharedMemorySize, L_SMEM);

    // 0) zero h/barrier; decode ids; transpose Wh; split W_out and Wx
    init_state_kernel<<<(2 * BATCH * HIDDEN + 255) / 256, 256>>>();
    decode_ids_kernel<<<(MROWS + 255) / 256, 256>>>(ids_raw);
    {
        dim3 tg(HIDDEN / 32, G4 / 32);
        transpose_wh_kernel<<<tg, dim3(32, 8)>>>(Wh);
    }
    transpose_split_kernel<<<dim3(VOCAB / 32, HIDDEN / 32), dim3(32, 8)>>>(
        W_out, (__nv_bfloat16*)p_wthi, (__nv_bfloat16*)p_wtlo, VOCAB);
    transpose_split_kernel<<<dim3(G4 / 32, HIDDEN / 32), dim3(32, 8)>>>(
        Wx, (__nv_bfloat16*)p_wxhi, (__nv_bfloat16*)p_wxlo, G4);

    // 1) bf16 embedding gather (emb rows = WT rows[ids]) into g_hs_hi/lo
    gather_emb_bf16_kernel<<<MROWS, 128>>>();

    // 2) x_gates = emb @ Wx + b_lstm via fused 3-product HMMA (no permute)
    mma_gemm_kernel<0><<<dim3(MROWS / 128, G4 / 128), 256, L_SMEM>>>(
        (const __nv_bfloat16*)p_hshi, (const __nv_bfloat16*)p_hslo,
        (const __nv_bfloat16*)p_wxhi, (const __nv_bfloat16*)p_wxlo,
        b_lstm, (float*)p_xg, G4);

    // 3) recurrence: persistent kernel, 512 steps, grid barrier per step
    lstm_persistent_kernel<<<LP_BLOCKS, 256, LP_SMEM_BYTES>>>();

    // 4) split hs to bf16 hi/lo (overwrites emb buffers — emb no longer needed)
    split_hs_kernel<<<(MROWS * HIDDEN / 4) / 256, 256>>>();

    // 5) logits = hs @ W_out + b_out via fused 3-product HMMA (with (b,s) permute)
    mma_gemm_kernel<1><<<dim3(MROWS / 128, VOCAB / 128), 256, L_SMEM>>>(
        (const __nv_bfloat16*)p_hshi, (const __nv_bfloat16*)p_hslo,
        (const __nv_bfloat16*)p_wthi, (const __nv_bfloat16*)p_wtlo,
        b_out, out, VOCAB);
}